// round 16
// baseline (speedup 1.0000x reference)
#include <cuda_runtime.h>
#include <math.h>

// Problem constants (fixed shapes per reference)
#define T_SEQ 16384
#define DDIM  1024

// ---------------- scratch (static device allocations) ----------------------------
__device__ float    g_xwx[T_SEQ * DDIM];   // X@Wx + bh, 64 MB
__device__ unsigned g_cnt[T_SEQ];          // per-step arrival counters (memset/launch)

// ---------------- fp32 SGEMM: C[M,N] = A[M,K] @ B[K,N] + bias[N] ----------------
__global__ __launch_bounds__(256, 2)
void sgemm_bias_kernel(const float* __restrict__ A, const float* __restrict__ B,
                       const float* __restrict__ bias, float* __restrict__ C,
                       int M, int N, int K) {
    __shared__ float As[8][128];
    __shared__ float Bs[8][128];

    const int bx = blockIdx.x;
    const int by = blockIdx.y;
    const int tid = threadIdx.x;

    const int rowA = tid >> 1;
    const int colA = (tid & 1) * 4;
    const int rowB = tid >> 5;
    const int colB = (tid & 31) * 4;

    const int tr = tid / 16;
    const int tc = tid % 16;

    float accum[8][8];
#pragma unroll
    for (int i = 0; i < 8; i++)
#pragma unroll
        for (int j = 0; j < 8; j++) accum[i][j] = 0.0f;

    const float* Aptr = A + (size_t)(by * 128) * K;
    const float* Bptr = B + bx * 128;

    for (int k0 = 0; k0 < K; k0 += 8) {
        float4 a4 = *(const float4*)(Aptr + (size_t)rowA * K + k0 + colA);
        As[colA + 0][rowA] = a4.x;
        As[colA + 1][rowA] = a4.y;
        As[colA + 2][rowA] = a4.z;
        As[colA + 3][rowA] = a4.w;
        float4 b4 = *(const float4*)(Bptr + (size_t)(k0 + rowB) * N + colB);
        *(float4*)&Bs[rowB][colB] = b4;
        __syncthreads();

#pragma unroll
        for (int k = 0; k < 8; k++) {
            float ra[8], rb[8];
            *(float4*)&ra[0] = *(const float4*)&As[k][tr * 8];
            *(float4*)&ra[4] = *(const float4*)&As[k][tr * 8 + 4];
            *(float4*)&rb[0] = *(const float4*)&Bs[k][tc * 8];
            *(float4*)&rb[4] = *(const float4*)&Bs[k][tc * 8 + 4];
#pragma unroll
            for (int i = 0; i < 8; i++)
#pragma unroll
                for (int j = 0; j < 8; j++)
                    accum[i][j] += ra[i] * rb[j];
        }
        __syncthreads();
    }

    const int cRow = by * 128 + tr * 8;
    const int cCol = bx * 128 + tc * 8;
    float bv[8];
#pragma unroll
    for (int j = 0; j < 8; j++) bv[j] = bias[cCol + j];

#pragma unroll
    for (int i = 0; i < 8; i++) {
        float4 v0, v1;
        v0.x = accum[i][0] + bv[0];
        v0.y = accum[i][1] + bv[1];
        v0.z = accum[i][2] + bv[2];
        v0.w = accum[i][3] + bv[3];
        v1.x = accum[i][4] + bv[4];
        v1.y = accum[i][5] + bv[5];
        v1.z = accum[i][6] + bv[6];
        v1.w = accum[i][7] + bv[7];
        *(float4*)&C[(size_t)(cRow + i) * N + cCol]     = v0;
        *(float4*)&C[(size_t)(cRow + i) * N + cCol + 4] = v1;
    }
}

// ---------------- fused persistent recurrence + y-GEMM ---------------------------
// ONE launch, 148 CTAs x 256 threads:
//  CTAs [0,32):   recurrence. CTA b owns 32 h-columns [32b, 32b+32); warp w
//                 (0..7) owns 4 columns. Identical per-warp structure to the
//                 R15 champion (direct same-word acquire poll, scalar stores,
//                 __syncwarp, smem acq_rel fan-in, red.release.gpu). Releases
//                 EVERY step so consumer CTAs can wait on final tiles.
//                 32 participants (vs 64) thins the per-step straggler tail.
//  CTAs [32,148): y-GEMM consumers. Each processes 128x128 tiles of
//                 Y = H @ Wy + by, waiting (acquire-poll via thread0 +
//                 __syncthreads relay) until the tile's last h row is
//                 released, loading H with __ldcg. Runs entirely in the
//                 recurrence's shadow on otherwise-idle SMs.
#define RNN_BLK   32
#define RNN_WARPS 8
#define GEMM_BLK  116
#define TOTAL_BLK (RNN_BLK + GEMM_BLK)

__device__ __forceinline__ float fast_tanh(float x) {
    // tanh(x) = 1 - 2/(e^{2x}+1); MUFU-based, ~1e-7 rel err (tolerance 1e-3).
    float e = __expf(2.0f * x);
    return 1.0f - __fdividef(2.0f, e + 1.0f);
}

__global__ __launch_bounds__(256, 1)
void fused_rnn_kernel(const float* __restrict__ Wh, const float* __restrict__ Wy,
                      const float* __restrict__ by, float* __restrict__ hidden,
                      float* __restrict__ ys) {
    __shared__ float As[8][128];
    __shared__ float Bs[8][128];
    __shared__ unsigned s_arrive;

    const int tid  = threadIdx.x;
    const int lane = tid & 31;
    const int warp = tid >> 5;

    if (blockIdx.x < RNN_BLK) {
        // ------------------------- recurrence path -------------------------
        const int cb = blockIdx.x * 32 + warp * 4;   // 4 owned output columns

        if (tid == 0) s_arrive = 0u;
        __syncthreads();
        const unsigned s_arrive_addr = (unsigned)__cvta_generic_to_shared(&s_arrive);

        // One-time: 4 Wh columns into registers. lane l holds rows k*128+4l..+3.
        float4 w[4][8];
#pragma unroll
        for (int c = 0; c < 4; c++) {
#pragma unroll
            for (int k = 0; k < 8; k++) {
                int i = k * 128 + lane * 4;
                w[c][k].x = Wh[(size_t)(i + 0) * DDIM + cb + c];
                w[c][k].y = Wh[(size_t)(i + 1) * DDIM + cb + c];
                w[c][k].z = Wh[(size_t)(i + 2) * DDIM + cb + c];
                w[c][k].w = Wh[(size_t)(i + 3) * DDIM + cb + c];
            }
        }

        float bias = (lane < 4) ? __ldcg(&g_xwx[(size_t)0 * DDIM + cb + lane]) : 0.0f;

        for (int t = 0; t < T_SEQ; t++) {
            float bias_next = 0.0f;
            if (t + 1 < T_SEQ && lane < 4)
                bias_next = __ldcg(&g_xwx[(size_t)(t + 1) * DDIM + cb + lane]);

            float a0 = 0.0f, a1 = 0.0f, a2 = 0.0f, a3 = 0.0f;
            if (t > 0) {
                // Direct same-word acquire poll (1 coalesced req/warp/round).
                const unsigned* cp = &g_cnt[t - 1];
                unsigned v;
                do {
                    asm volatile("ld.acquire.gpu.global.u32 %0, [%1];"
                                 : "=r"(v) : "l"(cp));
                } while (v < (unsigned)RNN_BLK);

                // Load full h_{t-1}: 8 independent LDG.128.cg per lane.
                const float4* hp = (const float4*)(hidden + (size_t)(t - 1) * DDIM);
                float4 h4[8];
#pragma unroll
                for (int k = 0; k < 8; k++)
                    h4[k] = __ldcg(hp + k * 32 + lane);

#pragma unroll
                for (int k = 0; k < 8; k++) {
                    a0 += h4[k].x * w[0][k].x + h4[k].y * w[0][k].y
                        + h4[k].z * w[0][k].z + h4[k].w * w[0][k].w;
                    a1 += h4[k].x * w[1][k].x + h4[k].y * w[1][k].y
                        + h4[k].z * w[1][k].z + h4[k].w * w[1][k].w;
                    a2 += h4[k].x * w[2][k].x + h4[k].y * w[2][k].y
                        + h4[k].z * w[2][k].z + h4[k].w * w[2][k].w;
                    a3 += h4[k].x * w[3][k].x + h4[k].y * w[3][k].y
                        + h4[k].z * w[3][k].z + h4[k].w * w[3][k].w;
                }
#pragma unroll
                for (int s = 16; s > 0; s >>= 1) {
                    a0 += __shfl_xor_sync(0xffffffffu, a0, s);
                    a1 += __shfl_xor_sync(0xffffffffu, a1, s);
                    a2 += __shfl_xor_sync(0xffffffffu, a2, s);
                    a3 += __shfl_xor_sync(0xffffffffu, a3, s);
                }
            }

            // lanes 0-3 tanh + store their own column (one coalesced 16B txn).
            float acc = (lane == 0) ? a0 : (lane == 1) ? a1 : (lane == 2) ? a2 : a3;
            if (lane < 4) {
                float hval = fast_tanh(acc + bias);
                asm volatile("st.global.cg.f32 [%0], %1;"
                             :: "l"(&hidden[(size_t)t * DDIM + cb + lane]),
                                "f"(hval) : "memory");
            }
            __syncwarp();   // orders lanes' stores before lane0's arrival

            if (lane == 0) {
                // CTA fan-in; last warp releases this CTA's step increment.
                // Released for EVERY t (y-GEMM consumers need the last rows).
                unsigned old;
                asm volatile("atom.acq_rel.cta.shared.add.u32 %0, [%1], 1;"
                             : "=r"(old) : "r"(s_arrive_addr));
                if (old == (unsigned)((t + 1) * RNN_WARPS - 1)) {
                    asm volatile("red.release.gpu.global.add.u32 [%0], 1;"
                                 :: "l"(&g_cnt[t]));
                }
            }
            bias = bias_next;
        }
    } else {
        // ------------------------- y-GEMM consumer path --------------------
        const int gbid = blockIdx.x - RNN_BLK;

        const int rowA = tid >> 1;
        const int colA = (tid & 1) * 4;
        const int rowB = tid >> 5;
        const int colB = (tid & 31) * 4;
        const int tr = tid / 16;
        const int tc = tid % 16;

        // 128 M-tiles x 8 N-tiles = 1024 tiles; stride over 116 CTAs keeps
        // each CTA's tile sequence ascending in M (waits mostly pre-satisfied).
        for (int tile = gbid; tile < (T_SEQ / 128) * 8; tile += GEMM_BLK) {
            const int mt = tile >> 3;
            const int nt = tile & 7;

            // Wait until all h rows of this M-tile are released.
            if (tid == 0) {
                const unsigned* cp = &g_cnt[mt * 128 + 127];
                unsigned v;
                do {
                    asm volatile("ld.acquire.gpu.global.u32 %0, [%1];"
                                 : "=r"(v) : "l"(cp));
                } while (v < (unsigned)RNN_BLK);
            }
            __syncthreads();   // relay thread0's acquired visibility to block

            float accum[8][8];
#pragma unroll
            for (int i = 0; i < 8; i++)
#pragma unroll
                for (int j = 0; j < 8; j++) accum[i][j] = 0.0f;

            const float* Aptr = hidden + (size_t)(mt * 128) * DDIM;
            const float* Bptr = Wy + nt * 128;

            for (int k0 = 0; k0 < DDIM; k0 += 8) {
                float4 a4 = __ldcg((const float4*)(Aptr + (size_t)rowA * DDIM + k0 + colA));
                As[colA + 0][rowA] = a4.x;
                As[colA + 1][rowA] = a4.y;
                As[colA + 2][rowA] = a4.z;
                As[colA + 3][rowA] = a4.w;
                float4 b4 = *(const float4*)(Bptr + (size_t)(k0 + rowB) * DDIM + colB);
                *(float4*)&Bs[rowB][colB] = b4;
                __syncthreads();

#pragma unroll
                for (int k = 0; k < 8; k++) {
                    float ra[8], rb[8];
                    *(float4*)&ra[0] = *(const float4*)&As[k][tr * 8];
                    *(float4*)&ra[4] = *(const float4*)&As[k][tr * 8 + 4];
                    *(float4*)&rb[0] = *(const float4*)&Bs[k][tc * 8];
                    *(float4*)&rb[4] = *(const float4*)&Bs[k][tc * 8 + 4];
#pragma unroll
                    for (int i = 0; i < 8; i++)
#pragma unroll
                        for (int j = 0; j < 8; j++)
                            accum[i][j] += ra[i] * rb[j];
                }
                __syncthreads();
            }

            const int cRow = mt * 128 + tr * 8;
            const int cCol = nt * 128 + tc * 8;
            float bv[8];
#pragma unroll
            for (int j = 0; j < 8; j++) bv[j] = by[cCol + j];

#pragma unroll
            for (int i = 0; i < 8; i++) {
                float4 v0, v1;
                v0.x = accum[i][0] + bv[0];
                v0.y = accum[i][1] + bv[1];
                v0.z = accum[i][2] + bv[2];
                v0.w = accum[i][3] + bv[3];
                v1.x = accum[i][4] + bv[4];
                v1.y = accum[i][5] + bv[5];
                v1.z = accum[i][6] + bv[6];
                v1.w = accum[i][7] + bv[7];
                *(float4*)&ys[(size_t)cRow * DDIM + (size_t)i * DDIM + cCol]     = v0;
                *(float4*)&ys[(size_t)cRow * DDIM + (size_t)i * DDIM + cCol + 4] = v1;
            }
        }
    }
}

// ---------------- launch ---------------------------------------------------------
extern "C" void kernel_launch(void* const* d_in, const int* in_sizes, int n_in,
                              void* d_out, int out_size) {
    const float* X  = (const float*)d_in[0];  // [T, D]
    const float* Wx = (const float*)d_in[1];  // [D, D]
    const float* Wh = (const float*)d_in[2];  // [D, D]
    const float* Wy = (const float*)d_in[3];  // [D, D]
    const float* bh = (const float*)d_in[4];  // [D]
    const float* by = (const float*)d_in[5];  // [D]

    float* out    = (float*)d_out;
    float* hidden = out;                         // [T, D]
    float* ys     = out + (size_t)T_SEQ * DDIM;  // [T, D]

    float* xwx_ptr = nullptr;
    unsigned* cnt_ptr = nullptr;
    cudaGetSymbolAddress((void**)&xwx_ptr, g_xwx);
    cudaGetSymbolAddress((void**)&cnt_ptr, g_cnt);

    // Reset per-step counters (graph-capturable memset node).
    cudaMemsetAsync(cnt_ptr, 0, T_SEQ * sizeof(unsigned));

    // 1) XWx = X @ Wx + bh
    {
        dim3 grid(DDIM / 128, T_SEQ / 128);
        sgemm_bias_kernel<<<grid, 256>>>(X, Wx, bh, xwx_ptr, T_SEQ, DDIM, DDIM);
    }

    // 2) Fused: recurrence (32 CTAs) + overlapped y-GEMM (116 CTAs).
    fused_rnn_kernel<<<TOTAL_BLK, 256>>>(Wh, Wy, by, hidden, ys);
}

// round 17
// speedup vs baseline: 1.0606x; 1.0606x over previous
#include <cuda_runtime.h>
#include <math.h>

// Problem constants (fixed shapes per reference)
#define T_SEQ 16384
#define DDIM  1024

// ---------------- scratch (static device allocations) ----------------------------
__device__ float    g_xwx[T_SEQ * DDIM];   // X@Wx + bh, 64 MB
__device__ unsigned g_cnt[T_SEQ];          // per-step arrival counters (memset/launch)

// ---------------- fp32 SGEMM: C[M,N] = A[M,K] @ B[K,N] + bias[N] ----------------
__global__ __launch_bounds__(256, 2)
void sgemm_bias_kernel(const float* __restrict__ A, const float* __restrict__ B,
                       const float* __restrict__ bias, float* __restrict__ C,
                       int M, int N, int K) {
    __shared__ float As[8][128];
    __shared__ float Bs[8][128];

    const int bx = blockIdx.x;
    const int by = blockIdx.y;
    const int tid = threadIdx.x;

    const int rowA = tid >> 1;
    const int colA = (tid & 1) * 4;
    const int rowB = tid >> 5;
    const int colB = (tid & 31) * 4;

    const int tr = tid / 16;
    const int tc = tid % 16;

    float accum[8][8];
#pragma unroll
    for (int i = 0; i < 8; i++)
#pragma unroll
        for (int j = 0; j < 8; j++) accum[i][j] = 0.0f;

    const float* Aptr = A + (size_t)(by * 128) * K;
    const float* Bptr = B + bx * 128;

    for (int k0 = 0; k0 < K; k0 += 8) {
        float4 a4 = *(const float4*)(Aptr + (size_t)rowA * K + k0 + colA);
        As[colA + 0][rowA] = a4.x;
        As[colA + 1][rowA] = a4.y;
        As[colA + 2][rowA] = a4.z;
        As[colA + 3][rowA] = a4.w;
        float4 b4 = *(const float4*)(Bptr + (size_t)(k0 + rowB) * N + colB);
        *(float4*)&Bs[rowB][colB] = b4;
        __syncthreads();

#pragma unroll
        for (int k = 0; k < 8; k++) {
            float ra[8], rb[8];
            *(float4*)&ra[0] = *(const float4*)&As[k][tr * 8];
            *(float4*)&ra[4] = *(const float4*)&As[k][tr * 8 + 4];
            *(float4*)&rb[0] = *(const float4*)&Bs[k][tc * 8];
            *(float4*)&rb[4] = *(const float4*)&Bs[k][tc * 8 + 4];
#pragma unroll
            for (int i = 0; i < 8; i++)
#pragma unroll
                for (int j = 0; j < 8; j++)
                    accum[i][j] += ra[i] * rb[j];
        }
        __syncthreads();
    }

    const int cRow = by * 128 + tr * 8;
    const int cCol = bx * 128 + tc * 8;
    float bv[8];
#pragma unroll
    for (int j = 0; j < 8; j++) bv[j] = bias[cCol + j];

#pragma unroll
    for (int i = 0; i < 8; i++) {
        float4 v0, v1;
        v0.x = accum[i][0] + bv[0];
        v0.y = accum[i][1] + bv[1];
        v0.z = accum[i][2] + bv[2];
        v0.w = accum[i][3] + bv[3];
        v1.x = accum[i][4] + bv[4];
        v1.y = accum[i][5] + bv[5];
        v1.z = accum[i][6] + bv[6];
        v1.w = accum[i][7] + bv[7];
        *(float4*)&C[(size_t)(cRow + i) * N + cCol]     = v0;
        *(float4*)&C[(size_t)(cRow + i) * N + cCol + 4] = v1;
    }
}

// ---------------- fused persistent recurrence + y-GEMM ---------------------------
// ONE launch, 148 CTAs x 256 threads:
//  CTAs [0,64):   recurrence, EXACT R15 champion structure: warps 0-3 active
//                 (warps 4-7 exit immediately), CTA b owns 16 h-columns
//                 [16b,16b+16), warp w owns 4. Direct same-word acquire poll,
//                 scalar stores + __syncwarp, 4-arrival smem acq_rel fan-in,
//                 red.release.gpu EVERY step (consumers need final rows).
//                 Intra-CTA sync uses bar.sync 0,128 (only 128 live threads).
//  CTAs [64,148): y-GEMM consumers: 128x128 tiles of Y = H @ Wy + by; wait
//                 via thread0 acquire-poll + __syncthreads relay until the
//                 tile's last h row is released; H loaded with __ldcg. Runs
//                 in the recurrence's shadow on otherwise-idle SMs.
#define RNN_BLK   64
#define RNN_WARPS 4
#define GEMM_BLK  84
#define TOTAL_BLK (RNN_BLK + GEMM_BLK)

__device__ __forceinline__ float fast_tanh(float x) {
    // tanh(x) = 1 - 2/(e^{2x}+1); MUFU-based, ~1e-7 rel err (tolerance 1e-3).
    float e = __expf(2.0f * x);
    return 1.0f - __fdividef(2.0f, e + 1.0f);
}

__global__ __launch_bounds__(256, 1)
void fused_rnn_kernel(const float* __restrict__ Wh, const float* __restrict__ Wy,
                      const float* __restrict__ by, float* __restrict__ hidden,
                      float* __restrict__ ys) {
    __shared__ float As[8][128];
    __shared__ float Bs[8][128];
    __shared__ unsigned s_arrive;

    const int tid  = threadIdx.x;
    const int lane = tid & 31;
    const int warp = tid >> 5;

    if (blockIdx.x < RNN_BLK) {
        // ------------------------- recurrence path (R15 exact) -------------
        if (warp >= RNN_WARPS) return;    // warps 4-7 idle off immediately

        const int cb = blockIdx.x * 16 + warp * 4;   // 4 owned output columns

        if (tid == 0) s_arrive = 0u;
        asm volatile("bar.sync 0, 128;" ::: "memory");   // 128 live threads
        const unsigned s_arrive_addr = (unsigned)__cvta_generic_to_shared(&s_arrive);

        // One-time: 4 Wh columns into registers. lane l holds rows k*128+4l..+3.
        float4 w[4][8];
#pragma unroll
        for (int c = 0; c < 4; c++) {
#pragma unroll
            for (int k = 0; k < 8; k++) {
                int i = k * 128 + lane * 4;
                w[c][k].x = Wh[(size_t)(i + 0) * DDIM + cb + c];
                w[c][k].y = Wh[(size_t)(i + 1) * DDIM + cb + c];
                w[c][k].z = Wh[(size_t)(i + 2) * DDIM + cb + c];
                w[c][k].w = Wh[(size_t)(i + 3) * DDIM + cb + c];
            }
        }

        float bias = (lane < 4) ? __ldcg(&g_xwx[(size_t)0 * DDIM + cb + lane]) : 0.0f;

        for (int t = 0; t < T_SEQ; t++) {
            float bias_next = 0.0f;
            if (t + 1 < T_SEQ && lane < 4)
                bias_next = __ldcg(&g_xwx[(size_t)(t + 1) * DDIM + cb + lane]);

            float a0 = 0.0f, a1 = 0.0f, a2 = 0.0f, a3 = 0.0f;
            if (t > 0) {
                // Direct same-word acquire poll (1 coalesced req/warp/round).
                const unsigned* cp = &g_cnt[t - 1];
                unsigned v;
                do {
                    asm volatile("ld.acquire.gpu.global.u32 %0, [%1];"
                                 : "=r"(v) : "l"(cp));
                } while (v < (unsigned)RNN_BLK);

                // Load full h_{t-1}: 8 independent LDG.128.cg per lane.
                const float4* hp = (const float4*)(hidden + (size_t)(t - 1) * DDIM);
                float4 h4[8];
#pragma unroll
                for (int k = 0; k < 8; k++)
                    h4[k] = __ldcg(hp + k * 32 + lane);

#pragma unroll
                for (int k = 0; k < 8; k++) {
                    a0 += h4[k].x * w[0][k].x + h4[k].y * w[0][k].y
                        + h4[k].z * w[0][k].z + h4[k].w * w[0][k].w;
                    a1 += h4[k].x * w[1][k].x + h4[k].y * w[1][k].y
                        + h4[k].z * w[1][k].z + h4[k].w * w[1][k].w;
                    a2 += h4[k].x * w[2][k].x + h4[k].y * w[2][k].y
                        + h4[k].z * w[2][k].z + h4[k].w * w[2][k].w;
                    a3 += h4[k].x * w[3][k].x + h4[k].y * w[3][k].y
                        + h4[k].z * w[3][k].z + h4[k].w * w[3][k].w;
                }
#pragma unroll
                for (int s = 16; s > 0; s >>= 1) {
                    a0 += __shfl_xor_sync(0xffffffffu, a0, s);
                    a1 += __shfl_xor_sync(0xffffffffu, a1, s);
                    a2 += __shfl_xor_sync(0xffffffffu, a2, s);
                    a3 += __shfl_xor_sync(0xffffffffu, a3, s);
                }
            }

            // lanes 0-3 tanh + store their own column (one coalesced 16B txn).
            float acc = (lane == 0) ? a0 : (lane == 1) ? a1 : (lane == 2) ? a2 : a3;
            if (lane < 4) {
                float hval = fast_tanh(acc + bias);
                asm volatile("st.global.cg.f32 [%0], %1;"
                             :: "l"(&hidden[(size_t)t * DDIM + cb + lane]),
                                "f"(hval) : "memory");
            }
            __syncwarp();   // orders lanes' stores before lane0's arrival

            if (lane == 0) {
                // CTA fan-in; last warp releases this CTA's step increment.
                // Released for EVERY t (y-GEMM consumers need the last rows).
                unsigned old;
                asm volatile("atom.acq_rel.cta.shared.add.u32 %0, [%1], 1;"
                             : "=r"(old) : "r"(s_arrive_addr));
                if (old == (unsigned)((t + 1) * RNN_WARPS - 1)) {
                    asm volatile("red.release.gpu.global.add.u32 [%0], 1;"
                                 :: "l"(&g_cnt[t]));
                }
            }
            bias = bias_next;
        }
    } else {
        // ------------------------- y-GEMM consumer path --------------------
        const int gbid = blockIdx.x - RNN_BLK;

        const int rowA = tid >> 1;
        const int colA = (tid & 1) * 4;
        const int rowB = tid >> 5;
        const int colB = (tid & 31) * 4;
        const int tr = tid / 16;
        const int tc = tid % 16;

        // 128 M-tiles x 8 N-tiles = 1024 tiles; stride over 84 CTAs keeps
        // each CTA's tile sequence ascending in M (waits mostly pre-satisfied).
        for (int tile = gbid; tile < (T_SEQ / 128) * 8; tile += GEMM_BLK) {
            const int mt = tile >> 3;
            const int nt = tile & 7;

            // Wait until all h rows of this M-tile are released.
            if (tid == 0) {
                const unsigned* cp = &g_cnt[mt * 128 + 127];
                unsigned v;
                do {
                    asm volatile("ld.acquire.gpu.global.u32 %0, [%1];"
                                 : "=r"(v) : "l"(cp));
                } while (v < (unsigned)RNN_BLK);
            }
            __syncthreads();   // relay thread0's acquired visibility to block

            float accum[8][8];
#pragma unroll
            for (int i = 0; i < 8; i++)
#pragma unroll
                for (int j = 0; j < 8; j++) accum[i][j] = 0.0f;

            const float* Aptr = hidden + (size_t)(mt * 128) * DDIM;
            const float* Bptr = Wy + nt * 128;

            for (int k0 = 0; k0 < DDIM; k0 += 8) {
                float4 a4 = __ldcg((const float4*)(Aptr + (size_t)rowA * DDIM + k0 + colA));
                As[colA + 0][rowA] = a4.x;
                As[colA + 1][rowA] = a4.y;
                As[colA + 2][rowA] = a4.z;
                As[colA + 3][rowA] = a4.w;
                float4 b4 = *(const float4*)(Bptr + (size_t)(k0 + rowB) * DDIM + colB);
                *(float4*)&Bs[rowB][colB] = b4;
                __syncthreads();

#pragma unroll
                for (int k = 0; k < 8; k++) {
                    float ra[8], rb[8];
                    *(float4*)&ra[0] = *(const float4*)&As[k][tr * 8];
                    *(float4*)&ra[4] = *(const float4*)&As[k][tr * 8 + 4];
                    *(float4*)&rb[0] = *(const float4*)&Bs[k][tc * 8];
                    *(float4*)&rb[4] = *(const float4*)&Bs[k][tc * 8 + 4];
#pragma unroll
                    for (int i = 0; i < 8; i++)
#pragma unroll
                        for (int j = 0; j < 8; j++)
                            accum[i][j] += ra[i] * rb[j];
                }
                __syncthreads();
            }

            const int cRow = mt * 128 + tr * 8;
            const int cCol = nt * 128 + tc * 8;
            float bv[8];
#pragma unroll
            for (int j = 0; j < 8; j++) bv[j] = by[cCol + j];

#pragma unroll
            for (int i = 0; i < 8; i++) {
                float4 v0, v1;
                v0.x = accum[i][0] + bv[0];
                v0.y = accum[i][1] + bv[1];
                v0.z = accum[i][2] + bv[2];
                v0.w = accum[i][3] + bv[3];
                v1.x = accum[i][4] + bv[4];
                v1.y = accum[i][5] + bv[5];
                v1.z = accum[i][6] + bv[6];
                v1.w = accum[i][7] + bv[7];
                *(float4*)&ys[(size_t)cRow * DDIM + (size_t)i * DDIM + cCol]     = v0;
                *(float4*)&ys[(size_t)cRow * DDIM + (size_t)i * DDIM + cCol + 4] = v1;
            }
        }
    }
}

// ---------------- launch ---------------------------------------------------------
extern "C" void kernel_launch(void* const* d_in, const int* in_sizes, int n_in,
                              void* d_out, int out_size) {
    const float* X  = (const float*)d_in[0];  // [T, D]
    const float* Wx = (const float*)d_in[1];  // [D, D]
    const float* Wh = (const float*)d_in[2];  // [D, D]
    const float* Wy = (const float*)d_in[3];  // [D, D]
    const float* bh = (const float*)d_in[4];  // [D]
    const float* by = (const float*)d_in[5];  // [D]

    float* out    = (float*)d_out;
    float* hidden = out;                         // [T, D]
    float* ys     = out + (size_t)T_SEQ * DDIM;  // [T, D]

    float* xwx_ptr = nullptr;
    unsigned* cnt_ptr = nullptr;
    cudaGetSymbolAddress((void**)&xwx_ptr, g_xwx);
    cudaGetSymbolAddress((void**)&cnt_ptr, g_cnt);

    // Reset per-step counters (graph-capturable memset node).
    cudaMemsetAsync(cnt_ptr, 0, T_SEQ * sizeof(unsigned));

    // 1) XWx = X @ Wx + bh
    {
        dim3 grid(DDIM / 128, T_SEQ / 128);
        sgemm_bias_kernel<<<grid, 256>>>(X, Wx, bh, xwx_ptr, T_SEQ, DDIM, DDIM);
    }

    // 2) Fused: recurrence (64 CTAs, R15-exact) + overlapped y-GEMM (84 CTAs).
    fused_rnn_kernel<<<TOTAL_BLK, 256>>>(Wh, Wy, by, hidden, ys);
}